// round 12
// baseline (speedup 1.0000x reference)
#include <cuda_runtime.h>
#include <cstdint>

#define HH 256
#define NN 64
#define LL 2048
#define PAD 66      // float2 row stride (even -> 16B-aligned rows)
#define TT 512

typedef unsigned long long u64;

__device__ __forceinline__ u64 fma2(u64 a, u64 b, u64 c) {
    u64 d;
    asm("fma.rn.f32x2 %0, %1, %2, %3;" : "=l"(d) : "l"(a), "l"(b), "l"(c));
    return d;
}
__device__ __forceinline__ u64 pack2(float lo, float hi) {
    u64 r;
    asm("mov.b64 %0, {%1, %2};" : "=l"(r) : "f"(lo), "f"(hi));
    return r;
}
__device__ __forceinline__ void unpack2(u64 v, float& lo, float& hi) {
    asm("mov.b64 {%0, %1}, %2;" : "=f"(lo), "=f"(hi) : "l"(v));
}

// ---------------------------------------------------------------------------
// In-place 64x64 complex square: buf <- buf * buf.
// 16x16 warp tiles: warp w -> rows (w>>2)*16 + {lr, lr+8}, cols (w&3)*16 + lc*4.
// ---------------------------------------------------------------------------
__device__ __forceinline__ void square_ip(float2* __restrict__ buf, int t) {
    const int lane = t & 31;
    const int w = t >> 5;
    const int r0 = (w >> 2) * 16 + (lane >> 2);
    const int j0 = (w & 3) * 16 + (lane & 3) * 4;
    u64 P[2][4], Q[2][4];
#pragma unroll
    for (int r = 0; r < 2; r++)
#pragma unroll
        for (int c = 0; c < 4; c++) { P[r][c] = 0; Q[r][c] = 0; }

    const u64* row0 = reinterpret_cast<const u64*>(buf + r0 * PAD);
    const u64* row1 = reinterpret_cast<const u64*>(buf + (r0 + 8) * PAD);

#pragma unroll 2
    for (int k = 0; k < 64; k += 2) {
        ulonglong2 a0 = *reinterpret_cast<const ulonglong2*>(row0 + k);
        ulonglong2 a1 = *reinterpret_cast<const ulonglong2*>(row1 + k);
#pragma unroll
        for (int kk = 0; kk < 2; kk++) {
            const u64 ap0 = kk ? a0.y : a0.x;
            const u64 ap1 = kk ? a1.y : a1.x;
            float a0r, a0i, a1r, a1i;
            unpack2(ap0, a0r, a0i);
            unpack2(ap1, a1r, a1i);
            u64 s0r = pack2(a0r, a0r), s0i = pack2(a0i, a0i);
            u64 s1r = pack2(a1r, a1r), s1i = pack2(a1i, a1i);
            const u64* bk = reinterpret_cast<const u64*>(buf + (k + kk) * PAD);
            ulonglong2 b01 = *reinterpret_cast<const ulonglong2*>(bk + j0);
            ulonglong2 b23 = *reinterpret_cast<const ulonglong2*>(bk + j0 + 2);
            P[0][0] = fma2(s0r, b01.x, P[0][0]); Q[0][0] = fma2(s0i, b01.x, Q[0][0]);
            P[0][1] = fma2(s0r, b01.y, P[0][1]); Q[0][1] = fma2(s0i, b01.y, Q[0][1]);
            P[0][2] = fma2(s0r, b23.x, P[0][2]); Q[0][2] = fma2(s0i, b23.x, Q[0][2]);
            P[0][3] = fma2(s0r, b23.y, P[0][3]); Q[0][3] = fma2(s0i, b23.y, Q[0][3]);
            P[1][0] = fma2(s1r, b01.x, P[1][0]); Q[1][0] = fma2(s1i, b01.x, Q[1][0]);
            P[1][1] = fma2(s1r, b01.y, P[1][1]); Q[1][1] = fma2(s1i, b01.y, Q[1][1]);
            P[1][2] = fma2(s1r, b23.x, P[1][2]); Q[1][2] = fma2(s1i, b23.x, Q[1][2]);
            P[1][3] = fma2(s1r, b23.y, P[1][3]); Q[1][3] = fma2(s1i, b23.y, Q[1][3]);
        }
    }
    __syncthreads();
#pragma unroll
    for (int r = 0; r < 2; r++) {
        const int rr = r0 + r * 8;
        float re[4], im[4];
#pragma unroll
        for (int c = 0; c < 4; c++) {
            float pl, ph, ql, qh;
            unpack2(P[r][c], pl, ph);
            unpack2(Q[r][c], ql, qh);
            re[c] = pl - qh; im[c] = ph + ql;
        }
        *reinterpret_cast<float4*>(buf + rr * PAD + j0) =
            make_float4(re[0], im[0], re[1], im[1]);
        *reinterpret_cast<float4*>(buf + rr * PAD + j0 + 2) =
            make_float4(re[2], im[2], re[3], im[3]);
    }
    __syncthreads();
}

// ---------------------------------------------------------------------------
// Tiled U doubling stage: U[S+j][:] = sum_k U[j][k] * E[k][:], j in [0,S).
// ---------------------------------------------------------------------------
template<int S>
__device__ __forceinline__ void ustage_t(float2* __restrict__ U,
                                         const float2* __restrict__ E, int t) {
    constexpr int RW  = (S < 8) ? S : 8;
    constexpr int LC  = 32 / RW;
    constexpr int CW  = 2 * LC;
    constexpr int NCB = 64 / CW;
    constexpr int NW  = (S / RW) * NCB;
    const int w = t >> 5;
    if (w >= NW) return;
    const int lane = t & 31;
    const int rb = w / NCB, cb = w % NCB;
    const int lr = lane / LC, lc = lane % LC;
    const int j  = rb * RW + lr;
    const int c0 = cb * CW + lc * 2;

    const u64* uj = reinterpret_cast<const u64*>(U + j * PAD);
    u64 P0 = 0, Q0 = 0, P1 = 0, Q1 = 0;
#pragma unroll 4
    for (int k = 0; k < 64; k += 2) {
        ulonglong2 up = *reinterpret_cast<const ulonglong2*>(uj + k);
#pragma unroll
        for (int kk = 0; kk < 2; kk++) {
            float ur, ui;
            unpack2(kk ? up.y : up.x, ur, ui);
            u64 sr = pack2(ur, ur), si = pack2(ui, ui);
            ulonglong2 e = *reinterpret_cast<const ulonglong2*>(
                reinterpret_cast<const u64*>(E + (k + kk) * PAD) + c0);
            P0 = fma2(sr, e.x, P0); Q0 = fma2(si, e.x, Q0);
            P1 = fma2(sr, e.y, P1); Q1 = fma2(si, e.y, Q1);
        }
    }
    float p0l, p0h, q0l, q0h, p1l, p1h, q1l, q1h;
    unpack2(P0, p0l, p0h); unpack2(Q0, q0l, q0h);
    unpack2(P1, p1l, p1h); unpack2(Q1, q1l, q1h);
    *reinterpret_cast<float4*>(U + (S + j) * PAD + c0) =
        make_float4(p0l - q0h, p0h + q0l, p1l - q1h, p1h + q1l);
}

// ---------------------------------------------------------------------------
// v-chain step: x_next = E32 * x (splat-format x), fused output dot.
// Splat layout: complex n -> u64 idx 2n + 2*(n>>3)  (18 u64 per 8-complex
// group; group == col segment). Chunk rotation c=(m+sg)&3 -> line index
// (9*sg + 2*c) mod 8 is a permutation of 0..7 for each m: conflict-free.
// ---------------------------------------------------------------------------
__device__ __forceinline__ void chain_step(
    const u64* __restrict__ xsrc, u64* __restrict__ xdst,
    const u64* e, const float2* uc, float* __restrict__ outh,
    int it, int i, int sg, int t, bool last)
{
    const u64* xs = xsrc + sg * 18;
    u64 P0 = 0, Q0 = 0, P1 = 0, Q1 = 0;
    float kp = 0.f;
#pragma unroll
    for (int m = 0; m < 4; m++) {
        const int c = (m + sg) & 3;
        ulonglong2 v0 = *reinterpret_cast<const ulonglong2*>(xs + 4 * c);
        ulonglong2 v1 = *reinterpret_cast<const ulonglong2*>(xs + 4 * c + 2);
        P0 = fma2(v0.x, e[2 * m], P0);
        Q0 = fma2(v0.y, e[2 * m], Q0);
        P1 = fma2(v1.x, e[2 * m + 1], P1);
        Q1 = fma2(v1.y, e[2 * m + 1], Q1);
        if (t < 256) {   // output dot on lower half only (upper was redundant)
            float xr0, xi0, xr1, xi1, dmy;
            unpack2(v0.x, xr0, dmy);
            unpack2(v0.y, xi0, dmy);
            unpack2(v1.x, xr1, dmy);
            unpack2(v1.y, xi1, dmy);
            kp += uc[2 * m].x * xr0 - uc[2 * m].y * xi0;
            kp += uc[2 * m + 1].x * xr1 - uc[2 * m + 1].y * xi1;
        }
    }
    if (t < 256) {
        kp += __shfl_xor_sync(0xffffffffu, kp, 1);
        kp += __shfl_xor_sync(0xffffffffu, kp, 2);
        kp += __shfl_xor_sync(0xffffffffu, kp, 4);
        if (sg == 0) outh[it * 32 + i] = kp;
    }
    if (!last) {
        float p0l, p0h, q0l, q0h, p1l, p1h, q1l, q1h;
        unpack2(P0, p0l, p0h); unpack2(Q0, q0l, q0h);
        unpack2(P1, p1l, p1h); unpack2(Q1, q1l, q1h);
        float re = (p0l - q0h) + (p1l - q1h);
        float im = (p0h + q0l) + (p1h + q1l);
        re += __shfl_xor_sync(0xffffffffu, re, 1);
        im += __shfl_xor_sync(0xffffffffu, im, 1);
        re += __shfl_xor_sync(0xffffffffu, re, 2);
        im += __shfl_xor_sync(0xffffffffu, im, 2);
        re += __shfl_xor_sync(0xffffffffu, re, 4);
        im += __shfl_xor_sync(0xffffffffu, im, 4);
        if (sg == 0)
            *reinterpret_cast<float4*>(xdst + (i >> 3) * 18 + 2 * (i & 7)) =
                make_float4(re, re, im, im);
    }
    __syncthreads();
}

// ---------------------------------------------------------------------------
// One block (512 threads) per head.
// ---------------------------------------------------------------------------
__global__ void __launch_bounds__(TT, 2) ssm_kernel(const float* __restrict__ A,
                                                    const float* __restrict__ B,
                                                    const float* __restrict__ C,
                                                    const float* __restrict__ logdt,
                                                    float* __restrict__ out) {
    extern __shared__ float2 sh[];
    float2* buf   = sh;                  // 64*PAD — matrix (in-place squares)
    float2* U     = buf + 64 * PAD;      // 32*PAD
    u64* xs0      = reinterpret_cast<u64*>(U + 32 * PAD);  // 144 u64 splat x
    u64* xs1      = xs0 + 144;                             // 144 u64
    float2* gbuf  = reinterpret_cast<float2*>(xs1 + 144);  // 2*64 (GJ col-k)
    float2* rkbuf = gbuf + 128;          // 2*64 (GJ row-k raw, dbl-buffered)
    float2* bv    = rkbuf + 128;         // 64

    const int t = threadIdx.x;
    const int h = blockIdx.x;
    const int i  = t >> 3;   // owned row (GJ, v-chain)
    const int sg = t & 7;    // owned col segment [8*sg, 8*sg+8)
    const int ro = sg >> 1;  // GJ rotation (proven conflict-free on rkbuf)
    const int pm0 = ro, pm1 = (1 + ro) & 3, pm2 = (2 + ro) & 3, pm3 = (3 + ro) & 3;

    const float dt = expf(__ldg(logdt + h));
    const float hd = 0.5f * dt;

    // stage inputs
    const float2* Ah = ((const float2*)A) + (size_t)h * NN * NN;
    for (int idx = t; idx < NN * NN; idx += TT) buf[idx] = Ah[idx];
    if (t < 64) {
        bv[t] = ((const float2*)B)[h * NN + t];
        U[t]  = ((const float2*)C)[h * NN + t];
    }
    __syncthreads();

    // registers <- A_back = I - dt/2 * Ac, physically rotated (GJ rotation)
    float2 R[8];
    {
        const float4* arow = reinterpret_cast<const float4*>(buf + i * 64) + sg * 4;
        const int pmv[4] = {pm0, pm1, pm2, pm3};
#pragma unroll
        for (int m = 0; m < 4; m++) {
            float4 a = arow[pmv[m]];
            int j0 = sg * 8 + 2 * pmv[m];
            R[2 * m]     = make_float2(((i == j0) ? 1.0f : 0.0f) - hd * a.x, -hd * a.y);
            R[2 * m + 1] = make_float2(((i == j0 + 1) ? 1.0f : 0.0f) - hd * a.z, -hd * a.w);
        }
    }
    __syncthreads();

    // ---- register-resident Gauss-Jordan inverse (no pivoting) ----
#pragma unroll 1
    for (int k = 0; k < NN; k++) {
        const int pb = (k & 1) * 64;
        const int kj = k & 7;
        const int pidx = 2 * (((kj >> 1) - ro) & 3) + (kj & 1);
        const bool own = (sg == (k >> 3));
        if (own) {
            float2 v = R[0];
#pragma unroll
            for (int q = 1; q < 8; q++) if (pidx == q) v = R[q];
            gbuf[pb + i] = v;
        }
        if (i == k) {
            float4* rk4w = reinterpret_cast<float4*>(rkbuf + pb) + sg * 4;
            rk4w[pm0] = make_float4(R[0].x, R[0].y, R[1].x, R[1].y);
            rk4w[pm1] = make_float4(R[2].x, R[2].y, R[3].x, R[3].y);
            rk4w[pm2] = make_float4(R[4].x, R[4].y, R[5].x, R[5].y);
            rk4w[pm3] = make_float4(R[6].x, R[6].y, R[7].x, R[7].y);
        }
        __syncthreads();
        float2 p = gbuf[pb + k];
        float inv = 1.0f / (p.x * p.x + p.y * p.y);
        float2 pinv = make_float2(p.x * inv, -p.y * inv);
        if (i == k) {
#pragma unroll
            for (int q = 0; q < 8; q++) {
                float2 r = R[q];
                R[q] = make_float2(r.x * pinv.x - r.y * pinv.y,
                                   r.x * pinv.y + r.y * pinv.x);
            }
            if (own) {
#pragma unroll
                for (int q = 0; q < 8; q++) if (pidx == q) R[q] = pinv;
            }
        } else {
            float2 gi = gbuf[pb + i];
            float2 fc = make_float2(gi.x * pinv.x - gi.y * pinv.y,
                                    gi.x * pinv.y + gi.y * pinv.x);
            const float4* rk4 = reinterpret_cast<const float4*>(rkbuf + pb) + sg * 4;
            const int pmv[4] = {pm0, pm1, pm2, pm3};
#pragma unroll
            for (int m = 0; m < 4; m++) {
                float4 rr = rk4[pmv[m]];
                float2 v0 = R[2 * m], v1 = R[2 * m + 1];
                v0.x -= fc.x * rr.x - fc.y * rr.y;
                v0.y -= fc.x * rr.y + fc.y * rr.x;
                v1.x -= fc.x * rr.z - fc.y * rr.w;
                v1.y -= fc.x * rr.w + fc.y * rr.z;
                R[2 * m] = v0; R[2 * m + 1] = v1;
            }
            if (own) {
                float2 nf = make_float2(-fc.x, -fc.y);
#pragma unroll
                for (int q = 0; q < 8; q++) if (pidx == q) R[q] = nf;
            }
        }
    }
    __syncthreads();

    // ---- dB = dt*inv*B -> xs0 in SPLAT format ----
    {
        const float4* bv4 = reinterpret_cast<const float4*>(bv) + sg * 4;
        const int pmv[4] = {pm0, pm1, pm2, pm3};
        float sr = 0.f, si = 0.f;
#pragma unroll
        for (int m = 0; m < 4; m++) {
            float4 bb = bv4[pmv[m]];
            float2 m0 = R[2 * m], m1 = R[2 * m + 1];
            sr += m0.x * bb.x - m0.y * bb.y + m1.x * bb.z - m1.y * bb.w;
            si += m0.x * bb.y + m0.y * bb.x + m1.x * bb.w + m1.y * bb.z;
        }
        sr += __shfl_xor_sync(0xffffffffu, sr, 1);
        si += __shfl_xor_sync(0xffffffffu, si, 1);
        sr += __shfl_xor_sync(0xffffffffu, sr, 2);
        si += __shfl_xor_sync(0xffffffffu, si, 2);
        sr += __shfl_xor_sync(0xffffffffu, sr, 4);
        si += __shfl_xor_sync(0xffffffffu, si, 4);
        if (sg == 0) {
            float fr = dt * sr, fi = dt * si;
            *reinterpret_cast<float4*>(xs0 + (i >> 3) * 18 + 2 * (i & 7)) =
                make_float4(fr, fr, fi, fi);
        }
    }
    // ---- dA = 2*inv - I -> buf (padded), rotated addressing ----
    {
        const int pmv[4] = {pm0, pm1, pm2, pm3};
#pragma unroll
        for (int m = 0; m < 4; m++) {
            int j0 = sg * 8 + 2 * pmv[m];
            float2 v0 = R[2 * m], v1 = R[2 * m + 1];
            *reinterpret_cast<float4*>(buf + i * PAD + j0) = make_float4(
                2.0f * v0.x - ((i == j0) ? 1.0f : 0.0f), 2.0f * v0.y,
                2.0f * v1.x - ((i == j0 + 1) ? 1.0f : 0.0f), 2.0f * v1.y);
        }
    }
    __syncthreads();

    // ---- fused powers + U doubling (E held in buf, squared in place) ----
    ustage_t<1>(U, buf, t);  square_ip(buf, t);   // E2,  U[1]
    ustage_t<2>(U, buf, t);  square_ip(buf, t);   // E4,  U[2..4)
    ustage_t<4>(U, buf, t);  square_ip(buf, t);   // E8,  U[4..8)
    ustage_t<8>(U, buf, t);  square_ip(buf, t);   // E16, U[8..16)
    ustage_t<16>(U, buf, t); square_ip(buf, t);   // E32, U[16..32)

    // ---- v-chain: E32 + U slices register-cached (rotation (m+sg)&3,
    //      matching the splat-x chunk rotation) ----
    u64 e[8];
    float2 uc[8];
    {
        const u64* er = reinterpret_cast<const u64*>(buf + i * PAD) + sg * 8;
        const float2* up = U + (i & 31) * PAD + sg * 8;
#pragma unroll
        for (int m = 0; m < 4; m++) {
            const int c = (m + sg) & 3;
            ulonglong2 ev = *reinterpret_cast<const ulonglong2*>(er + 2 * c);
            e[2 * m] = ev.x; e[2 * m + 1] = ev.y;
            float4 uv = *reinterpret_cast<const float4*>(up + 2 * c);
            uc[2 * m] = make_float2(uv.x, uv.y);
            uc[2 * m + 1] = make_float2(uv.z, uv.w);
        }
    }
    float* outh = out + (size_t)h * LL;

#pragma unroll 1
    for (int it = 0; it < 64; it += 2) {
        chain_step(xs0, xs1, e, uc, outh, it,     i, sg, t, false);
        chain_step(xs1, xs0, e, uc, outh, it + 1, i, sg, t, (it + 1) == 63);
    }
}

// ---------------------------------------------------------------------------

static const int SSM_SMEM =
    (96 * PAD + 128 + 128 + 64) * (int)sizeof(float2) + 2 * 144 * (int)sizeof(u64);

extern "C" void kernel_launch(void* const* d_in, const int* in_sizes, int n_in,
                              void* d_out, int out_size) {
    (void)in_sizes; (void)n_in; (void)out_size;
    const float* A     = (const float*)d_in[0];
    const float* B     = (const float*)d_in[1];
    const float* C     = (const float*)d_in[2];
    const float* logdt = (const float*)d_in[3];

    cudaFuncSetAttribute(ssm_kernel, cudaFuncAttributeMaxDynamicSharedMemorySize,
                         SSM_SMEM);
    ssm_kernel<<<HH, TT, SSM_SMEM>>>(A, B, C, logdt, (float*)d_out);
}

// round 13
// speedup vs baseline: 1.1068x; 1.1068x over previous
#include <cuda_runtime.h>
#include <cstdint>

#define HH 256
#define NN 64
#define LL 2048
#define PAD 66      // float2 row stride (even -> 16B-aligned rows)
#define TT 512

typedef unsigned long long u64;

__device__ __forceinline__ u64 fma2(u64 a, u64 b, u64 c) {
    u64 d;
    asm("fma.rn.f32x2 %0, %1, %2, %3;" : "=l"(d) : "l"(a), "l"(b), "l"(c));
    return d;
}
__device__ __forceinline__ u64 pack2(float lo, float hi) {
    u64 r;
    asm("mov.b64 %0, {%1, %2};" : "=l"(r) : "f"(lo), "f"(hi));
    return r;
}
__device__ __forceinline__ void unpack2(u64 v, float& lo, float& hi) {
    asm("mov.b64 {%0, %1}, %2;" : "=f"(lo), "=f"(hi) : "l"(v));
}

// ---------------------------------------------------------------------------
// In-place 64x64 complex square: buf <- buf * buf.
// 16x16 warp tiles: warp w -> rows (w>>2)*16 + {lr, lr+8}, cols (w&3)*16 + lc*4.
// ---------------------------------------------------------------------------
__device__ __forceinline__ void square_ip(float2* __restrict__ buf, int t) {
    const int lane = t & 31;
    const int w = t >> 5;
    const int r0 = (w >> 2) * 16 + (lane >> 2);
    const int j0 = (w & 3) * 16 + (lane & 3) * 4;
    u64 P[2][4], Q[2][4];
#pragma unroll
    for (int r = 0; r < 2; r++)
#pragma unroll
        for (int c = 0; c < 4; c++) { P[r][c] = 0; Q[r][c] = 0; }

    const u64* row0 = reinterpret_cast<const u64*>(buf + r0 * PAD);
    const u64* row1 = reinterpret_cast<const u64*>(buf + (r0 + 8) * PAD);

#pragma unroll 2
    for (int k = 0; k < 64; k += 2) {
        ulonglong2 a0 = *reinterpret_cast<const ulonglong2*>(row0 + k);
        ulonglong2 a1 = *reinterpret_cast<const ulonglong2*>(row1 + k);
#pragma unroll
        for (int kk = 0; kk < 2; kk++) {
            const u64 ap0 = kk ? a0.y : a0.x;
            const u64 ap1 = kk ? a1.y : a1.x;
            float a0r, a0i, a1r, a1i;
            unpack2(ap0, a0r, a0i);
            unpack2(ap1, a1r, a1i);
            u64 s0r = pack2(a0r, a0r), s0i = pack2(a0i, a0i);
            u64 s1r = pack2(a1r, a1r), s1i = pack2(a1i, a1i);
            const u64* bk = reinterpret_cast<const u64*>(buf + (k + kk) * PAD);
            ulonglong2 b01 = *reinterpret_cast<const ulonglong2*>(bk + j0);
            ulonglong2 b23 = *reinterpret_cast<const ulonglong2*>(bk + j0 + 2);
            P[0][0] = fma2(s0r, b01.x, P[0][0]); Q[0][0] = fma2(s0i, b01.x, Q[0][0]);
            P[0][1] = fma2(s0r, b01.y, P[0][1]); Q[0][1] = fma2(s0i, b01.y, Q[0][1]);
            P[0][2] = fma2(s0r, b23.x, P[0][2]); Q[0][2] = fma2(s0i, b23.x, Q[0][2]);
            P[0][3] = fma2(s0r, b23.y, P[0][3]); Q[0][3] = fma2(s0i, b23.y, Q[0][3]);
            P[1][0] = fma2(s1r, b01.x, P[1][0]); Q[1][0] = fma2(s1i, b01.x, Q[1][0]);
            P[1][1] = fma2(s1r, b01.y, P[1][1]); Q[1][1] = fma2(s1i, b01.y, Q[1][1]);
            P[1][2] = fma2(s1r, b23.x, P[1][2]); Q[1][2] = fma2(s1i, b23.x, Q[1][2]);
            P[1][3] = fma2(s1r, b23.y, P[1][3]); Q[1][3] = fma2(s1i, b23.y, Q[1][3]);
        }
    }
    __syncthreads();
#pragma unroll
    for (int r = 0; r < 2; r++) {
        const int rr = r0 + r * 8;
        float re[4], im[4];
#pragma unroll
        for (int c = 0; c < 4; c++) {
            float pl, ph, ql, qh;
            unpack2(P[r][c], pl, ph);
            unpack2(Q[r][c], ql, qh);
            re[c] = pl - qh; im[c] = ph + ql;
        }
        *reinterpret_cast<float4*>(buf + rr * PAD + j0) =
            make_float4(re[0], im[0], re[1], im[1]);
        *reinterpret_cast<float4*>(buf + rr * PAD + j0 + 2) =
            make_float4(re[2], im[2], re[3], im[3]);
    }
    __syncthreads();
}

// ---------------------------------------------------------------------------
// Tiled U doubling stage: U[S+j][:] = sum_k U[j][k] * E[k][:], j in [0,S).
// Tile loop handles NW > 16 (S=32 -> 32 warp-tiles over 16 warps).
// ---------------------------------------------------------------------------
template<int S>
__device__ __forceinline__ void ustage_t(float2* __restrict__ U,
                                         const float2* __restrict__ E, int t) {
    constexpr int RW  = (S < 8) ? S : 8;
    constexpr int LC  = 32 / RW;
    constexpr int CW  = 2 * LC;
    constexpr int NCB = 64 / CW;
    constexpr int NW  = (S / RW) * NCB;
    const int w = t >> 5;
    const int lane = t & 31;
    const int lr = lane / LC, lc = lane % LC;

#pragma unroll
    for (int tile = w; tile < NW; tile += 16) {
        const int rb = tile / NCB, cb = tile % NCB;
        const int j  = rb * RW + lr;
        const int c0 = cb * CW + lc * 2;

        const u64* uj = reinterpret_cast<const u64*>(U + j * PAD);
        u64 P0 = 0, Q0 = 0, P1 = 0, Q1 = 0;
#pragma unroll 4
        for (int k = 0; k < 64; k += 2) {
            ulonglong2 up = *reinterpret_cast<const ulonglong2*>(uj + k);
#pragma unroll
            for (int kk = 0; kk < 2; kk++) {
                float ur, ui;
                unpack2(kk ? up.y : up.x, ur, ui);
                u64 sr = pack2(ur, ur), si = pack2(ui, ui);
                ulonglong2 e = *reinterpret_cast<const ulonglong2*>(
                    reinterpret_cast<const u64*>(E + (k + kk) * PAD) + c0);
                P0 = fma2(sr, e.x, P0); Q0 = fma2(si, e.x, Q0);
                P1 = fma2(sr, e.y, P1); Q1 = fma2(si, e.y, Q1);
            }
        }
        float p0l, p0h, q0l, q0h, p1l, p1h, q1l, q1h;
        unpack2(P0, p0l, p0h); unpack2(Q0, q0l, q0h);
        unpack2(P1, p1l, p1h); unpack2(Q1, q1l, q1h);
        *reinterpret_cast<float4*>(U + (S + j) * PAD + c0) =
            make_float4(p0l - q0h, p0h + q0l, p1l - q1h, p1h + q1l);
    }
}

// ---------------------------------------------------------------------------
// One block (512 threads) per head. GJ slice physically rotated in registers
// (perm(m)=(m+sg>>1)&3); rotation lives only in smem addresses.
// Krylov split 64 x 32: 64 u-vectors (6 doubling stages), 32-step E64 chain.
// ---------------------------------------------------------------------------
__global__ void __launch_bounds__(TT, 2) ssm_kernel(const float* __restrict__ A,
                                                    const float* __restrict__ B,
                                                    const float* __restrict__ C,
                                                    const float* __restrict__ logdt,
                                                    float* __restrict__ out) {
    extern __shared__ float2 sh[];
    float2* buf   = sh;                  // 64*PAD — matrix (in-place squares)
    float2* U     = buf + 64 * PAD;      // 64*PAD — 64 u-vectors
    float2* xbuf0 = U + 64 * PAD;        // 64
    float2* xbuf1 = xbuf0 + 64;          // 64
    float2* gbuf  = xbuf1 + 64;          // 2*64 col-k factors (dbl-buffered)
    float2* rkbuf = gbuf + 128;          // 2*64 row-k raw (dbl-buffered)
    float2* bv    = rkbuf + 128;         // 64

    const int t = threadIdx.x;
    const int h = blockIdx.x;
    const int i  = t >> 3;   // owned row (GJ, v-chain, output)
    const int sg = t & 7;    // owned col segment [8*sg, 8*sg+8)
    const int ro = sg >> 1;  // per-thread rotation (constant)
    const int pm0 = ro, pm1 = (1 + ro) & 3, pm2 = (2 + ro) & 3, pm3 = (3 + ro) & 3;

    const float dt = expf(__ldg(logdt + h));
    const float hd = 0.5f * dt;

    // stage inputs
    const float2* Ah = ((const float2*)A) + (size_t)h * NN * NN;
    for (int idx = t; idx < NN * NN; idx += TT) buf[idx] = Ah[idx];
    if (t < 64) {
        bv[t] = ((const float2*)B)[h * NN + t];
        U[t]  = ((const float2*)C)[h * NN + t];
    }
    __syncthreads();

    // registers <- A_back = I - dt/2 * Ac, physically rotated
    float2 R[8];
    {
        const float4* arow = reinterpret_cast<const float4*>(buf + i * 64) + sg * 4;
        const int pmv[4] = {pm0, pm1, pm2, pm3};
#pragma unroll
        for (int m = 0; m < 4; m++) {
            float4 a = arow[pmv[m]];
            int j0 = sg * 8 + 2 * pmv[m];
            R[2 * m]     = make_float2(((i == j0) ? 1.0f : 0.0f) - hd * a.x, -hd * a.y);
            R[2 * m + 1] = make_float2(((i == j0 + 1) ? 1.0f : 0.0f) - hd * a.z, -hd * a.w);
        }
    }
    __syncthreads();

    // ---- register-resident Gauss-Jordan inverse (no pivoting) ----
#pragma unroll 1
    for (int k = 0; k < NN; k++) {
        const int pb = (k & 1) * 64;
        const int kj = k & 7;
        const int pidx = 2 * (((kj >> 1) - ro) & 3) + (kj & 1);
        const bool own = (sg == (k >> 3));
        if (own) {
            float2 v = R[0];
#pragma unroll
            for (int q = 1; q < 8; q++) if (pidx == q) v = R[q];
            gbuf[pb + i] = v;
        }
        if (i == k) {
            float4* rk4w = reinterpret_cast<float4*>(rkbuf + pb) + sg * 4;
            rk4w[pm0] = make_float4(R[0].x, R[0].y, R[1].x, R[1].y);
            rk4w[pm1] = make_float4(R[2].x, R[2].y, R[3].x, R[3].y);
            rk4w[pm2] = make_float4(R[4].x, R[4].y, R[5].x, R[5].y);
            rk4w[pm3] = make_float4(R[6].x, R[6].y, R[7].x, R[7].y);
        }
        __syncthreads();
        float2 p = gbuf[pb + k];
        float inv = 1.0f / (p.x * p.x + p.y * p.y);
        float2 pinv = make_float2(p.x * inv, -p.y * inv);
        if (i == k) {
#pragma unroll
            for (int q = 0; q < 8; q++) {
                float2 r = R[q];
                R[q] = make_float2(r.x * pinv.x - r.y * pinv.y,
                                   r.x * pinv.y + r.y * pinv.x);
            }
            if (own) {
#pragma unroll
                for (int q = 0; q < 8; q++) if (pidx == q) R[q] = pinv;
            }
        } else {
            float2 gi = gbuf[pb + i];
            float2 fc = make_float2(gi.x * pinv.x - gi.y * pinv.y,
                                    gi.x * pinv.y + gi.y * pinv.x);
            const float4* rk4 = reinterpret_cast<const float4*>(rkbuf + pb) + sg * 4;
            const int pmv[4] = {pm0, pm1, pm2, pm3};
#pragma unroll
            for (int m = 0; m < 4; m++) {
                float4 rr = rk4[pmv[m]];
                float2 v0 = R[2 * m], v1 = R[2 * m + 1];
                v0.x -= fc.x * rr.x - fc.y * rr.y;
                v0.y -= fc.x * rr.y + fc.y * rr.x;
                v1.x -= fc.x * rr.z - fc.y * rr.w;
                v1.y -= fc.x * rr.w + fc.y * rr.z;
                R[2 * m] = v0; R[2 * m + 1] = v1;
            }
            if (own) {
                float2 nf = make_float2(-fc.x, -fc.y);
#pragma unroll
                for (int q = 0; q < 8; q++) if (pidx == q) R[q] = nf;
            }
        }
    }
    __syncthreads();

    // ---- dB = dt*inv*B (order-independent dot; rotated addressing) ----
    {
        const float4* bv4 = reinterpret_cast<const float4*>(bv) + sg * 4;
        const int pmv[4] = {pm0, pm1, pm2, pm3};
        float sr = 0.f, si = 0.f;
#pragma unroll
        for (int m = 0; m < 4; m++) {
            float4 bb = bv4[pmv[m]];
            float2 m0 = R[2 * m], m1 = R[2 * m + 1];
            sr += m0.x * bb.x - m0.y * bb.y + m1.x * bb.z - m1.y * bb.w;
            si += m0.x * bb.y + m0.y * bb.x + m1.x * bb.w + m1.y * bb.z;
        }
        sr += __shfl_xor_sync(0xffffffffu, sr, 1);
        si += __shfl_xor_sync(0xffffffffu, si, 1);
        sr += __shfl_xor_sync(0xffffffffu, sr, 2);
        si += __shfl_xor_sync(0xffffffffu, si, 2);
        sr += __shfl_xor_sync(0xffffffffu, sr, 4);
        si += __shfl_xor_sync(0xffffffffu, si, 4);
        if (sg == 0) xbuf0[i] = make_float2(dt * sr, dt * si);
    }
    // ---- dA = 2*inv - I -> buf (padded), rotated addressing ----
    {
        const int pmv[4] = {pm0, pm1, pm2, pm3};
#pragma unroll
        for (int m = 0; m < 4; m++) {
            int j0 = sg * 8 + 2 * pmv[m];
            float2 v0 = R[2 * m], v1 = R[2 * m + 1];
            *reinterpret_cast<float4*>(buf + i * PAD + j0) = make_float4(
                2.0f * v0.x - ((i == j0) ? 1.0f : 0.0f), 2.0f * v0.y,
                2.0f * v1.x - ((i == j0 + 1) ? 1.0f : 0.0f), 2.0f * v1.y);
        }
    }
    __syncthreads();

    // ---- fused powers + U doubling: 64 u-vectors, E64 for the chain ----
    ustage_t<1>(U, buf, t);  square_ip(buf, t);   // E2,  U[1]
    ustage_t<2>(U, buf, t);  square_ip(buf, t);   // E4,  U[2..4)
    ustage_t<4>(U, buf, t);  square_ip(buf, t);   // E8,  U[4..8)
    ustage_t<8>(U, buf, t);  square_ip(buf, t);   // E16, U[8..16)
    ustage_t<16>(U, buf, t); square_ip(buf, t);   // E32, U[16..32)
    ustage_t<32>(U, buf, t); square_ip(buf, t);   // E64, U[32..64)

    // ---- v-chain: 32 iters; E64 + U slices register-cached, rotated ----
    u64 e[8];
    float2 uc[8];
    {
        const u64* er = reinterpret_cast<const u64*>(buf + i * PAD) + sg * 8;
        const float4* up = reinterpret_cast<const float4*>(U + i * PAD) + sg * 4;
        const int pmv[4] = {pm0, pm1, pm2, pm3};
#pragma unroll
        for (int m = 0; m < 4; m++) {
            ulonglong2 ev = *reinterpret_cast<const ulonglong2*>(er + 2 * pmv[m]);
            e[2 * m] = ev.x; e[2 * m + 1] = ev.y;
            float4 uv = up[pmv[m]];
            uc[2 * m] = make_float2(uv.x, uv.y);
            uc[2 * m + 1] = make_float2(uv.z, uv.w);
        }
    }
    float* outh = out + (size_t)h * LL;
    float2* xcur = xbuf0;
    float2* xnxt = xbuf1;

#pragma unroll 1
    for (int it = 0; it < 32; it++) {
        const float4* xc4 = reinterpret_cast<const float4*>(xcur) + sg * 4;
        u64 P0 = 0, Q0 = 0, P1 = 0, Q1 = 0;
        float kp = 0.f;
        {
            const int pmv[4] = {pm0, pm1, pm2, pm3};
#pragma unroll
            for (int m = 0; m < 4; m++) {
                float4 x2 = xc4[pmv[m]];
                P0 = fma2(pack2(x2.x, x2.x), e[2 * m], P0);
                Q0 = fma2(pack2(x2.y, x2.y), e[2 * m], Q0);
                P1 = fma2(pack2(x2.z, x2.z), e[2 * m + 1], P1);
                Q1 = fma2(pack2(x2.w, x2.w), e[2 * m + 1], Q1);
                kp += uc[2 * m].x * x2.x - uc[2 * m].y * x2.y;
                kp += uc[2 * m + 1].x * x2.z - uc[2 * m + 1].y * x2.w;
            }
        }
        // output: k[64*it + i] = Re(U[i] . v), reduce over 8 segments
        kp += __shfl_xor_sync(0xffffffffu, kp, 1);
        kp += __shfl_xor_sync(0xffffffffu, kp, 2);
        kp += __shfl_xor_sync(0xffffffffu, kp, 4);
        if (sg == 0) outh[it * 64 + i] = kp;
        // v <- E64 * v
        if (it < 31) {
            float p0l, p0h, q0l, q0h, p1l, p1h, q1l, q1h;
            unpack2(P0, p0l, p0h); unpack2(Q0, q0l, q0h);
            unpack2(P1, p1l, p1h); unpack2(Q1, q1l, q1h);
            float re = (p0l - q0h) + (p1l - q1h);
            float im = (p0h + q0l) + (p1h + q1l);
            re += __shfl_xor_sync(0xffffffffu, re, 1);
            im += __shfl_xor_sync(0xffffffffu, im, 1);
            re += __shfl_xor_sync(0xffffffffu, re, 2);
            im += __shfl_xor_sync(0xffffffffu, im, 2);
            re += __shfl_xor_sync(0xffffffffu, re, 4);
            im += __shfl_xor_sync(0xffffffffu, im, 4);
            if (sg == 0) xnxt[i] = make_float2(re, im);
            __syncthreads();
        }
        float2* tmp = xcur; xcur = xnxt; xnxt = tmp;
    }
}

// ---------------------------------------------------------------------------

static const int SSM_SMEM =
    (128 * PAD + 2 * 64 + 2 * 64 + 2 * 64 + 64) * (int)sizeof(float2);

extern "C" void kernel_launch(void* const* d_in, const int* in_sizes, int n_in,
                              void* d_out, int out_size) {
    (void)in_sizes; (void)n_in; (void)out_size;
    const float* A     = (const float*)d_in[0];
    const float* B     = (const float*)d_in[1];
    const float* C     = (const float*)d_in[2];
    const float* logdt = (const float*)d_in[3];

    cudaFuncSetAttribute(ssm_kernel, cudaFuncAttributeMaxDynamicSharedMemorySize,
                         SSM_SMEM);
    ssm_kernel<<<HH, TT, SSM_SMEM>>>(A, B, C, logdt, (float*)d_out);
}